// round 6
// baseline (speedup 1.0000x reference)
#include <cuda_runtime.h>

#define OVERLAP_T 0.5f
#define VAR0 0.1f
#define VAR1 0.2f

#define BMAX 64
#define PMAX 32768
#define OMAX 64
#define NBLK (PMAX/256)
#define BUF1 8192
#define BUF2 1024
// dynamic smem layout (uints): sd[PMAX] | buf1[BUF1] | buf2[BUF2] | hist[2048] | sfx[2048]
#define DSMEM_WORDS (PMAX + BUF1 + BUF2 + 2048 + 2048)

// Scratch (static device arrays; zero-initialized at load; each run leaves
// g_key/g_done zeroed again so graph replays see clean state)
__device__ float               g_ce[BMAX * PMAX];
__device__ unsigned long long  g_key[BMAX * OMAX];
__device__ int                 g_npos[BMAX];
__device__ float               g_pl[BMAX * NBLK];
__device__ float               g_pc[BMAX * NBLK];
__device__ int                 g_pn[BMAX * NBLK];
__device__ float               g_fl[BMAX];
__device__ float               g_fc[BMAX];
__device__ float               g_cneg[BMAX];
__device__ unsigned            g_done;

__device__ __forceinline__ float iou_one(float4 t, float ta,
                                         float px0, float py0, float px1, float py1,
                                         float pa) {
    float lx = fmaxf(t.x, px0), ly = fmaxf(t.y, py0);
    float rx = fminf(t.z, px1), ry = fminf(t.w, py1);
    float w = fmaxf(rx - lx, 0.0f), h = fmaxf(ry - ly, 0.0f);
    float inter = w * h;
    float den = ta + pa - inter;
    return __fdividef(inter, den);
}

__device__ __forceinline__ float sl1_of(float4 l, float4 pr, float4 t) {
    float gcx = ((t.x + t.z) * 0.5f - pr.x) / (VAR0 * pr.z);
    float gcy = ((t.y + t.w) * 0.5f - pr.y) / (VAR0 * pr.w);
    float gw  = __logf((t.z - t.x) / pr.z) * (1.0f / VAR1);
    float gh  = __logf((t.w - t.y) / pr.w) * (1.0f / VAR1);
    float d0 = l.x - gcx, d1 = l.y - gcy, d2 = l.z - gw, d3 = l.w - gh;
    float a0 = fabsf(d0), a1 = fabsf(d1), a2 = fabsf(d2), a3 = fabsf(d3);
    float s0 = (a0 < 1.0f) ? 0.5f * d0 * d0 : a0 - 0.5f;
    float s1 = (a1 < 1.0f) ? 0.5f * d1 * d1 : a1 - 0.5f;
    float s2 = (a2 < 1.0f) ? 0.5f * d2 * d2 : a2 - 0.5f;
    float s3 = (a3 < 1.0f) ? 0.5f * d3 * d3 : a3 - 0.5f;
    return (s0 + s1) + (s2 + s3);
}

__device__ __forceinline__ float lse2(float2 c) {
    float mx = fmaxf(c.x, c.y);
    float mn = fminf(c.x, c.y);
    return mx + __logf(1.0f + __expf(mn - mx));
}

// ---------------------------------------------------------------------------
// Fused match + loss. Per-truth filter is seeded from the global g_key so
// later waves skip the warp reduction almost always (monotone-safe: a stale
// smaller threshold only causes extra work; atomicMax guards correctness).
// ---------------------------------------------------------------------------
__global__ __launch_bounds__(256)
void k_main(const float* __restrict__ loc,
            const float* __restrict__ conf,
            const float* __restrict__ priors,
            const float* __restrict__ targets,
            int P, int O) {
    int b    = blockIdx.y;
    int tid  = threadIdx.x;
    int lane = tid & 31;
    int p    = blockIdx.x * blockDim.x + tid;

    __shared__ float4 tb[OMAX];
    __shared__ float  ta_s[OMAX];
    __shared__ unsigned long long skey[OMAX];
    __shared__ unsigned long long seed[OMAX];

    if (tid < O) {
        const float* t = targets + ((long)b * O + tid) * 5;
        float4 v = make_float4(t[0], t[1], t[2], t[3]);
        tb[tid]   = v;
        ta_s[tid] = (v.z - v.x) * (v.w - v.y);
        unsigned long long s0 = g_key[b * OMAX + tid];   // warm seed
        skey[tid] = s0;
        seed[tid] = s0;
    }
    __syncthreads();

    float4 pr = reinterpret_cast<const float4*>(priors)[p];
    float px0 = pr.x - pr.z * 0.5f;
    float py0 = pr.y - pr.w * 0.5f;
    float px1 = pr.x + pr.z * 0.5f;
    float py1 = pr.y + pr.w * 0.5f;
    float pa  = (px1 - px0) * (py1 - py0);

    float best = -1.0f;
    int   besto = 0;

    const unsigned* skey_hi = reinterpret_cast<const unsigned*>(skey);

    for (int o = 0; o < O; o++) {
        float iou = iou_one(tb[o], ta_s[o], px0, py0, px1, py1, pa);
        if (iou > best) { best = iou; besto = o; }

        unsigned ib = __float_as_uint(iou);
        if (__any_sync(0xffffffffu, ib >= skey_hi[2 * o + 1])) {
            float m = iou;
            #pragma unroll
            for (int off = 16; off; off >>= 1)
                m = fmaxf(m, __shfl_xor_sync(0xffffffffu, m, off));
            unsigned win = __ballot_sync(0xffffffffu, iou == m);
            if (lane == 0) {
                int src = __ffs(win) - 1;
                unsigned long long key =
                    ((unsigned long long)__float_as_uint(m) << 32) |
                    (unsigned int)(~(unsigned int)(p + src));
                if (key > skey[o]) atomicMax(&skey[o], key);
            }
        }
    }

    long ip = (long)b * P + p;
    int ct = (best >= OVERLAP_T) ? 1 : 0;

    float2 c = reinterpret_cast<const float2*>(conf)[ip];
    float lse = lse2(c);

    float ll = 0.0f, cp = 0.0f, ce_neg;
    int np = 0;
    if (ct) {
        np = 1;
        cp = lse - c.y;
        ce_neg = 0.0f;
        float4 l = reinterpret_cast<const float4*>(loc)[ip];
        ll = sl1_of(l, pr, tb[besto]);
    } else {
        ce_neg = lse - c.x;
    }
    g_ce[ip] = ce_neg;

    #pragma unroll
    for (int off = 16; off; off >>= 1) {
        ll += __shfl_xor_sync(0xffffffffu, ll, off);
        cp += __shfl_xor_sync(0xffffffffu, cp, off);
        np += __shfl_xor_sync(0xffffffffu, np, off);
    }
    __shared__ float wl[8], wc[8];
    __shared__ int   wn[8];
    if (lane == 0) { int w = tid >> 5; wl[w] = ll; wc[w] = cp; wn[w] = np; }
    __syncthreads();
    if (tid == 0) {
        float a = 0.f, cc = 0.f; int nn = 0;
        #pragma unroll
        for (int w = 0; w < 8; w++) { a += wl[w]; cc += wc[w]; nn += wn[w]; }
        int bi = b * gridDim.x + blockIdx.x;
        g_pl[bi] = a; g_pc[bi] = cc; g_pn[bi] = nn;
    }
    // merge only if this block actually improved past its seed
    if (tid < O && skey[tid] > seed[tid])
        atomicMax(&g_key[b * OMAX + tid], skey[tid]);
}

// ---------------------------------------------------------------------------
// Fused fixup + radix-select top-k + (last block) final reduction.
// Warp-aggregated histogram atomics and buffer appends.
// ---------------------------------------------------------------------------
__global__ __launch_bounds__(1024)
void k_topk(const float* __restrict__ loc,
            const float* __restrict__ conf,
            const float* __restrict__ priors,
            const float* __restrict__ targets,
            float* __restrict__ out,
            int P, int O, int nb, int B) {
    extern __shared__ unsigned dyn[];
    unsigned* sd   = dyn;                 // P staged values
    unsigned* buf1 = dyn + P;             // BUF1
    unsigned* buf2 = buf1 + BUF1;         // BUF2
    unsigned* hist = buf2 + BUF2;         // 2048
    unsigned* sfx  = hist + 2048;         // 2048

    __shared__ unsigned csum[64], cadd[64];
    __shared__ int      ps[OMAX];
    __shared__ float    fred[32];
    __shared__ int      ired[32];
    __shared__ double   dredA[32], dredC[32];
    __shared__ float    s_dl, s_dc;
    __shared__ int      s_dn, s_np, s_krem, s_chosen, s_last;
    __shared__ unsigned s_above, s_cnt1, s_cnt2;

    int b    = blockIdx.x;
    int tid  = threadIdx.x;
    int lane = tid & 31;
    int wrp  = tid >> 5;
    unsigned lmask = (1u << lane) - 1u;

    // ---------------- fixup prologue ----------------
    if (tid == 0) { s_dl = 0.f; s_dc = 0.f; s_dn = 0; s_cnt1 = 0u; s_cnt2 = 0u; }
    int np = 0;
    for (int j = tid; j < nb; j += 1024) np += g_pn[b * nb + j];
    #pragma unroll
    for (int off = 16; off; off >>= 1) np += __shfl_xor_sync(0xffffffffu, np, off);
    if (lane == 0) ired[wrp] = np;
    if (tid < O) {
        ps[tid] = (int)(~(unsigned int)(g_key[b * OMAX + tid] & 0xffffffffull));
        g_key[b * OMAX + tid] = 0ull;   // reset for next graph replay
    }
    __syncthreads();
    if (tid == 0) {
        int acc0 = 0;
        #pragma unroll
        for (int w = 0; w < 32; w++) acc0 += ired[w];
        s_np = acc0;
    }

    if (tid < O) {
        int p = ps[tid];
        bool dup = false;
        for (int o2 = tid + 1; o2 < O; o2++) if (ps[o2] == p) dup = true;
        if (!dup) {
            float4 pr = reinterpret_cast<const float4*>(priors)[p];
            float px0 = pr.x - pr.z * 0.5f;
            float py0 = pr.y - pr.w * 0.5f;
            float px1 = pr.x + pr.z * 0.5f;
            float py1 = pr.y + pr.w * 0.5f;
            float pa  = (px1 - px0) * (py1 - py0);

            float best = -1.0f; int bo = 0;
            for (int oo = 0; oo < O; oo++) {
                const float* tt = targets + ((long)b * O + oo) * 5;
                float4 t = make_float4(tt[0], tt[1], tt[2], tt[3]);
                float ta = (t.z - t.x) * (t.w - t.y);
                float iou = iou_one(t, ta, px0, py0, px1, py1, pa);
                if (iou > best) { best = iou; bo = oo; }
            }
            int ct = (best >= OVERLAP_T) ? 1 : 0;

            long ip = (long)b * P + p;
            float4 l = reinterpret_cast<const float4*>(loc)[ip];
            const float* tf = targets + ((long)b * O + tid) * 5;
            float4 tnew = make_float4(tf[0], tf[1], tf[2], tf[3]);
            float sl_new = sl1_of(l, pr, tnew);

            if (ct) {
                const float* to = targets + ((long)b * O + bo) * 5;
                float4 told = make_float4(to[0], to[1], to[2], to[3]);
                atomicAdd(&s_dl, sl_new - sl1_of(l, pr, told));
            } else {
                float2 c = reinterpret_cast<const float2*>(conf)[ip];
                float lse = lse2(c);
                atomicAdd(&s_dl, sl_new);
                atomicAdd(&s_dc, lse - c.y);
                atomicAdd(&s_dn, 1);
                g_ce[ip] = 0.0f;   // ordered before the load pass by __syncthreads
            }
        }
    }
    for (int i = tid; i < 2048; i += 1024) hist[i] = 0u;
    __syncthreads();

    int npos = s_np + s_dn;
    int k = 3 * npos; if (k > P - 1) k = P - 1;
    if (tid == 0) {
        g_npos[b] = npos;
        g_fl[b] = s_dl;
        g_fc[b] = s_dc;
        s_krem = k;
    }
    __syncthreads();

    float acc = 0.0f;
    int c1 = 0, c2 = 0, c3 = 0;

    if (k > 0) {
        const float* v = g_ce + (long)b * P;

        // ---- pass A: load + round-1 histogram (bits[31:21], 2048 bins),
        //      warp-aggregated atomics ----
        for (int i = tid; i < P; i += 1024) {
            unsigned u = __float_as_uint(v[i]);
            sd[i] = u;
            unsigned bin = u >> 21;
            unsigned grp = __match_any_sync(0xffffffffu, bin);
            if (lane == (int)(__ffs(grp) - 1))
                atomicAdd(&hist[bin], (unsigned)__popc(grp));
        }
        __syncthreads();

        // ---- selection helper: parallel suffix scan + crossing find ----
        #define SELECT_BIN(NBINS)                                               \
        {                                                                       \
            for (int i = tid; i < (NBINS); i += 1024) {                         \
                unsigned val = hist[i];                                         \
                _Pragma("unroll")                                               \
                for (int off = 1; off < 32; off <<= 1) {                        \
                    unsigned t2 = __shfl_down_sync(0xffffffffu, val, off);      \
                    if (lane + off < 32) val += t2;                             \
                }                                                               \
                sfx[i] = val;                                                   \
                if (lane == 0) csum[i >> 5] = val;                              \
            }                                                                   \
            __syncthreads();                                                    \
            int nch = (NBINS) >> 5;                                             \
            if (tid < nch) {                                                    \
                unsigned add = 0;                                               \
                for (int j = tid + 1; j < nch; j++) add += csum[j];             \
                cadd[tid] = add;                                                \
            }                                                                   \
            __syncthreads();                                                    \
            for (int i = tid; i < (NBINS); i += 1024) sfx[i] += cadd[i >> 5];   \
            __syncthreads();                                                    \
            int krem = s_krem;                                                  \
            for (int i = tid; i < (NBINS); i += 1024) {                         \
                unsigned s  = sfx[i];                                           \
                unsigned sn = (i + 1 < (NBINS)) ? sfx[i + 1] : 0u;              \
                if ((int)s >= krem && (int)sn < krem) {                         \
                    s_chosen = i; s_above = sn;                                 \
                }                                                               \
            }                                                                   \
            __syncthreads();                                                    \
            if (tid == 0) s_krem -= (int)s_above;                               \
        }

        SELECT_BIN(2048);
        c1 = s_chosen;
        for (int i = tid; i < 2048; i += 1024) hist[i] = 0u;
        __syncthreads();

        // ---- pass B: accumulate bins>c1; compact bin==c1 (warp-aggregated
        //      append) + round-2 hist (warp-aggregated) ----
        for (int i = tid; i < P; i += 1024) {
            unsigned u = sd[i];
            int bin = (int)(u >> 21);
            if (bin > c1) acc += __uint_as_float(u);
            bool sel = (bin == c1);
            unsigned vote = __ballot_sync(0xffffffffu, sel);
            if (vote) {
                unsigned cnt = __popc(vote);
                unsigned basepos = 0;
                if (lane == 0) basepos = atomicAdd(&s_cnt1, cnt);
                basepos = __shfl_sync(0xffffffffu, basepos, 0);
                if (sel) {
                    unsigned pos = basepos + __popc(vote & lmask);
                    if (pos < BUF1) buf1[pos] = u;
                    unsigned bin2 = (u >> 10) & 0x7FFu;
                    unsigned grp = __match_any_sync(vote, bin2);
                    if ((lane == (int)(__ffs(grp) - 1)))
                        atomicAdd(&hist[bin2], (unsigned)__popc(grp));
                }
            }
        }
        __syncthreads();

        SELECT_BIN(2048);
        c2 = s_chosen;
        unsigned S1 = s_cnt1;
        if (tid < 1024) hist[tid] = 0u;
        __syncthreads();

        // ---- pass C: among survivors, bins2>c2 → acc, ==c2 → compact ----
        if (S1 <= BUF1) {
            unsigned S1r = (S1 + 31u) & ~31u;   // keep warps converged
            for (unsigned i = tid; i < S1r; i += 1024) {
                bool live = (i < S1);
                unsigned u = live ? buf1[i] : 0u;
                int bin2 = live ? (int)((u >> 10) & 0x7FFu) : -1;
                if (bin2 > c2) acc += __uint_as_float(u);
                bool sel = (bin2 == c2);
                unsigned vote = __ballot_sync(0xffffffffu, sel);
                if (vote) {
                    unsigned cnt = __popc(vote);
                    unsigned basepos = 0;
                    if (lane == 0) basepos = atomicAdd(&s_cnt2, cnt);
                    basepos = __shfl_sync(0xffffffffu, basepos, 0);
                    if (sel) {
                        unsigned pos = basepos + __popc(vote & lmask);
                        if (pos < BUF2) buf2[pos] = u;
                        unsigned bin3 = u & 0x3FFu;
                        unsigned grp = __match_any_sync(vote, bin3);
                        if ((lane == (int)(__ffs(grp) - 1)))
                            atomicAdd(&hist[bin3], (unsigned)__popc(grp));
                    }
                }
            }
        } else {
            for (int i = tid; i < P; i += 1024) {
                unsigned u = sd[i];
                if ((int)(u >> 21) != c1) continue;
                int bin2 = (int)((u >> 10) & 0x7FFu);
                if (bin2 > c2) acc += __uint_as_float(u);
                else if (bin2 == c2) {
                    unsigned pos = atomicAdd(&s_cnt2, 1u);
                    if (pos < BUF2) buf2[pos] = u;
                    atomicAdd(&hist[u & 0x3FFu], 1u);
                }
            }
        }
        __syncthreads();

        SELECT_BIN(1024);
        c3 = s_chosen;
        unsigned S2 = s_cnt2;
        __syncthreads();

        // ---- pass D: final strictly-greater among exact-tie bin ----
        if (S2 <= BUF2) {
            for (unsigned i = tid; i < S2; i += 1024) {
                unsigned u = buf2[i];
                if ((int)(u & 0x3FFu) > c3) acc += __uint_as_float(u);
            }
        } else {
            for (int i = tid; i < P; i += 1024) {
                unsigned u = sd[i];
                if ((int)(u >> 21) == c1 && (int)((u >> 10) & 0x7FFu) == c2 &&
                    (int)(u & 0x3FFu) > c3)
                    acc += __uint_as_float(u);
            }
        }

        // block reduce acc
        #pragma unroll
        for (int off = 16; off; off >>= 1)
            acc += __shfl_xor_sync(0xffffffffu, acc, off);
        if (lane == 0) fred[wrp] = acc;
        __syncthreads();
        if (tid == 0) {
            float tot = 0.f;
            #pragma unroll
            for (int w = 0; w < 32; w++) tot += fred[w];
            unsigned tbits = ((unsigned)c1 << 21) | ((unsigned)c2 << 10) | (unsigned)c3;
            g_cneg[b] = tot + (float)s_krem * __uint_as_float(tbits);
        }
    } else {
        if (tid == 0) g_cneg[b] = 0.0f;
    }

    // ---------------- last-block final reduction ----------------
    if (tid == 0) {
        __threadfence();
        unsigned old = atomicAdd(&g_done, 1u);
        s_last = (old == (unsigned)(B - 1));
    }
    __syncthreads();
    if (!s_last) return;
    __threadfence();

    double a = 0.0, cc = 0.0;
    int n = 0;
    int tot = B * nb;
    for (int i = tid; i < tot; i += 1024) { a += (double)g_pl[i]; cc += (double)g_pc[i]; }
    for (int i = tid; i < B; i += 1024) {
        a  += (double)g_fl[i];
        cc += (double)g_fc[i] + (double)g_cneg[i];
        n  += g_npos[i];
    }
    #pragma unroll
    for (int off = 16; off; off >>= 1) {
        a  += __shfl_xor_sync(0xffffffffu, a, off);
        cc += __shfl_xor_sync(0xffffffffu, cc, off);
        n  += __shfl_xor_sync(0xffffffffu, n, off);
    }
    if (lane == 0) { dredA[wrp] = a; dredC[wrp] = cc; ired[wrp] = n; }
    __syncthreads();
    if (tid == 0) {
        double ta = 0.0, tc = 0.0; int tn = 0;
        #pragma unroll
        for (int w = 0; w < 32; w++) { ta += dredA[w]; tc += dredC[w]; tn += ired[w]; }
        double N = (double)tn;
        if (N < 1.0) N = 1.0;
        out[0] = (float)(ta / N);
        out[1] = (float)(tc / N);
        g_done = 0u;                    // reset for next graph replay
    }
}

extern "C" void kernel_launch(void* const* d_in, const int* in_sizes, int n_in,
                              void* d_out, int out_size) {
    const float* loc     = (const float*)d_in[0];
    const float* conf    = (const float*)d_in[1];
    const float* priors  = (const float*)d_in[2];
    const float* targets = (const float*)d_in[3];
    float* out = (float*)d_out;

    int P = in_sizes[2] / 4;
    int B = in_sizes[0] / (P * 4);
    int O = in_sizes[3] / (B * 5);
    int nb = (P + 255) / 256;

    static int smem_set = 0;
    if (!smem_set) {
        cudaFuncSetAttribute(k_topk, cudaFuncAttributeMaxDynamicSharedMemorySize,
                             DSMEM_WORDS * 4);
        smem_set = 1;
    }

    dim3 grid(nb, B);
    k_main<<<grid, 256>>>(loc, conf, priors, targets, P, O);
    k_topk<<<B, 1024, (P + BUF1 + BUF2 + 2048 + 2048) * 4>>>(
        loc, conf, priors, targets, out, P, O, nb, B);
}

// round 7
// speedup vs baseline: 1.2624x; 1.2624x over previous
#include <cuda_runtime.h>

#define OVERLAP_T 0.5f
#define VAR0 0.1f
#define VAR1 0.2f

#define BMAX 64
#define PMAX 32768
#define OMAX 64
#define NBLK (PMAX/256)
#define BUF1 8192
#define BUF2 1024
// dynamic smem layout (uints): sd[PMAX] | buf1[BUF1] | buf2[BUF2] | hist[2048] | sfx[2048]
#define DSMEM_WORDS (PMAX + BUF1 + BUF2 + 2048 + 2048)

// Scratch (static device arrays; zero-initialized at load; each run leaves
// g_key/g_done zeroed again so graph replays see clean state)
__device__ float               g_ce[BMAX * PMAX];
__device__ unsigned long long  g_key[BMAX * OMAX];
__device__ int                 g_npos[BMAX];
__device__ float               g_pl[BMAX * NBLK];
__device__ float               g_pc[BMAX * NBLK];
__device__ int                 g_pn[BMAX * NBLK];
__device__ float               g_fl[BMAX];
__device__ float               g_fc[BMAX];
__device__ float               g_cneg[BMAX];
__device__ unsigned            g_done;

__device__ __forceinline__ float iou_one(float4 t, float ta,
                                         float px0, float py0, float px1, float py1,
                                         float pa) {
    float lx = fmaxf(t.x, px0), ly = fmaxf(t.y, py0);
    float rx = fminf(t.z, px1), ry = fminf(t.w, py1);
    float w = fmaxf(rx - lx, 0.0f), h = fmaxf(ry - ly, 0.0f);
    float inter = w * h;
    float den = ta + pa - inter;
    return __fdividef(inter, den);
}

__device__ __forceinline__ float sl1_of(float4 l, float4 pr, float4 t) {
    float gcx = ((t.x + t.z) * 0.5f - pr.x) / (VAR0 * pr.z);
    float gcy = ((t.y + t.w) * 0.5f - pr.y) / (VAR0 * pr.w);
    float gw  = __logf((t.z - t.x) / pr.z) * (1.0f / VAR1);
    float gh  = __logf((t.w - t.y) / pr.w) * (1.0f / VAR1);
    float d0 = l.x - gcx, d1 = l.y - gcy, d2 = l.z - gw, d3 = l.w - gh;
    float a0 = fabsf(d0), a1 = fabsf(d1), a2 = fabsf(d2), a3 = fabsf(d3);
    float s0 = (a0 < 1.0f) ? 0.5f * d0 * d0 : a0 - 0.5f;
    float s1 = (a1 < 1.0f) ? 0.5f * d1 * d1 : a1 - 0.5f;
    float s2 = (a2 < 1.0f) ? 0.5f * d2 * d2 : a2 - 0.5f;
    float s3 = (a3 < 1.0f) ? 0.5f * d3 * d3 : a3 - 0.5f;
    return (s0 + s1) + (s2 + s3);
}

__device__ __forceinline__ float lse2(float2 c) {
    float mx = fmaxf(c.x, c.y);
    float mn = fminf(c.x, c.y);
    return mx + __logf(1.0f + __expf(mn - mx));
}

// ---------------------------------------------------------------------------
// Fused match + loss with per-truth early-out filter. (R5 form — no seeding)
// ---------------------------------------------------------------------------
__global__ __launch_bounds__(256)
void k_main(const float* __restrict__ loc,
            const float* __restrict__ conf,
            const float* __restrict__ priors,
            const float* __restrict__ targets,
            int P, int O) {
    int b    = blockIdx.y;
    int tid  = threadIdx.x;
    int lane = tid & 31;
    int p    = blockIdx.x * blockDim.x + tid;

    __shared__ float4 tb[OMAX];
    __shared__ float  ta_s[OMAX];
    __shared__ unsigned long long skey[OMAX];

    if (tid < O) {
        const float* t = targets + ((long)b * O + tid) * 5;
        float4 v = make_float4(t[0], t[1], t[2], t[3]);
        tb[tid]   = v;
        ta_s[tid] = (v.z - v.x) * (v.w - v.y);
        skey[tid] = 0ull;
    }
    __syncthreads();

    float4 pr = reinterpret_cast<const float4*>(priors)[p];
    float px0 = pr.x - pr.z * 0.5f;
    float py0 = pr.y - pr.w * 0.5f;
    float px1 = pr.x + pr.z * 0.5f;
    float py1 = pr.y + pr.w * 0.5f;
    float pa  = (px1 - px0) * (py1 - py0);

    float best = -1.0f;
    int   besto = 0;

    const unsigned* skey_hi = reinterpret_cast<const unsigned*>(skey);

    for (int o = 0; o < O; o++) {
        float iou = iou_one(tb[o], ta_s[o], px0, py0, px1, py1, pa);
        if (iou > best) { best = iou; besto = o; }

        unsigned ib = __float_as_uint(iou);
        if (__any_sync(0xffffffffu, ib >= skey_hi[2 * o + 1])) {
            float m = iou;
            #pragma unroll
            for (int off = 16; off; off >>= 1)
                m = fmaxf(m, __shfl_xor_sync(0xffffffffu, m, off));
            unsigned win = __ballot_sync(0xffffffffu, iou == m);
            if (lane == 0) {
                int src = __ffs(win) - 1;
                unsigned long long key =
                    ((unsigned long long)__float_as_uint(m) << 32) |
                    (unsigned int)(~(unsigned int)(p + src));
                if (key > skey[o]) atomicMax(&skey[o], key);
            }
        }
    }

    long ip = (long)b * P + p;
    int ct = (best >= OVERLAP_T) ? 1 : 0;

    float2 c = reinterpret_cast<const float2*>(conf)[ip];
    float lse = lse2(c);

    float ll = 0.0f, cp = 0.0f, ce_neg;
    int np = 0;
    if (ct) {
        np = 1;
        cp = lse - c.y;
        ce_neg = 0.0f;
        float4 l = reinterpret_cast<const float4*>(loc)[ip];
        ll = sl1_of(l, pr, tb[besto]);
    } else {
        ce_neg = lse - c.x;
    }
    g_ce[ip] = ce_neg;

    #pragma unroll
    for (int off = 16; off; off >>= 1) {
        ll += __shfl_xor_sync(0xffffffffu, ll, off);
        cp += __shfl_xor_sync(0xffffffffu, cp, off);
        np += __shfl_xor_sync(0xffffffffu, np, off);
    }
    __shared__ float wl[8], wc[8];
    __shared__ int   wn[8];
    if (lane == 0) { int w = tid >> 5; wl[w] = ll; wc[w] = cp; wn[w] = np; }
    __syncthreads();
    if (tid == 0) {
        float a = 0.f, cc = 0.f; int nn = 0;
        #pragma unroll
        for (int w = 0; w < 8; w++) { a += wl[w]; cc += wc[w]; nn += wn[w]; }
        int bi = b * gridDim.x + blockIdx.x;
        g_pl[bi] = a; g_pc[bi] = cc; g_pn[bi] = nn;
    }
    if (tid < O) atomicMax(&g_key[b * OMAX + tid], skey[tid]);
}

// ---------------------------------------------------------------------------
// Fused fixup + radix-select top-k + (last block) final reduction.
// Passes A/B vectorized (uint4); plain per-element smem atomics.
// ---------------------------------------------------------------------------
__global__ __launch_bounds__(1024)
void k_topk(const float* __restrict__ loc,
            const float* __restrict__ conf,
            const float* __restrict__ priors,
            const float* __restrict__ targets,
            float* __restrict__ out,
            int P, int O, int nb, int B) {
    extern __shared__ unsigned dyn[];
    unsigned* sd   = dyn;                 // P staged values
    unsigned* buf1 = dyn + P;             // BUF1
    unsigned* buf2 = buf1 + BUF1;         // BUF2
    unsigned* hist = buf2 + BUF2;         // 2048
    unsigned* sfx  = hist + 2048;         // 2048

    __shared__ unsigned csum[64], cadd[64];
    __shared__ int      ps[OMAX];
    __shared__ float    fred[32];
    __shared__ int      ired[32];
    __shared__ double   dredA[32], dredC[32];
    __shared__ float    s_dl, s_dc;
    __shared__ int      s_dn, s_np, s_krem, s_chosen, s_last;
    __shared__ unsigned s_above, s_cnt1, s_cnt2;

    int b    = blockIdx.x;
    int tid  = threadIdx.x;
    int lane = tid & 31;
    int wrp  = tid >> 5;

    // ---------------- fixup prologue ----------------
    if (tid == 0) { s_dl = 0.f; s_dc = 0.f; s_dn = 0; s_cnt1 = 0u; s_cnt2 = 0u; }
    int np = 0;
    for (int j = tid; j < nb; j += 1024) np += g_pn[b * nb + j];
    #pragma unroll
    for (int off = 16; off; off >>= 1) np += __shfl_xor_sync(0xffffffffu, np, off);
    if (lane == 0) ired[wrp] = np;
    if (tid < O) {
        ps[tid] = (int)(~(unsigned int)(g_key[b * OMAX + tid] & 0xffffffffull));
        g_key[b * OMAX + tid] = 0ull;   // reset for next graph replay
    }
    __syncthreads();
    if (tid == 0) {
        int acc0 = 0;
        #pragma unroll
        for (int w = 0; w < 32; w++) acc0 += ired[w];
        s_np = acc0;
    }

    if (tid < O) {
        int p = ps[tid];
        bool dup = false;
        for (int o2 = tid + 1; o2 < O; o2++) if (ps[o2] == p) dup = true;
        if (!dup) {
            float4 pr = reinterpret_cast<const float4*>(priors)[p];
            float px0 = pr.x - pr.z * 0.5f;
            float py0 = pr.y - pr.w * 0.5f;
            float px1 = pr.x + pr.z * 0.5f;
            float py1 = pr.y + pr.w * 0.5f;
            float pa  = (px1 - px0) * (py1 - py0);

            float best = -1.0f; int bo = 0;
            for (int oo = 0; oo < O; oo++) {
                const float* tt = targets + ((long)b * O + oo) * 5;
                float4 t = make_float4(tt[0], tt[1], tt[2], tt[3]);
                float ta = (t.z - t.x) * (t.w - t.y);
                float iou = iou_one(t, ta, px0, py0, px1, py1, pa);
                if (iou > best) { best = iou; bo = oo; }
            }
            int ct = (best >= OVERLAP_T) ? 1 : 0;

            long ip = (long)b * P + p;
            float4 l = reinterpret_cast<const float4*>(loc)[ip];
            const float* tf = targets + ((long)b * O + tid) * 5;
            float4 tnew = make_float4(tf[0], tf[1], tf[2], tf[3]);
            float sl_new = sl1_of(l, pr, tnew);

            if (ct) {
                const float* to = targets + ((long)b * O + bo) * 5;
                float4 told = make_float4(to[0], to[1], to[2], to[3]);
                atomicAdd(&s_dl, sl_new - sl1_of(l, pr, told));
            } else {
                float2 c = reinterpret_cast<const float2*>(conf)[ip];
                float lse = lse2(c);
                atomicAdd(&s_dl, sl_new);
                atomicAdd(&s_dc, lse - c.y);
                atomicAdd(&s_dn, 1);
                g_ce[ip] = 0.0f;   // ordered before the load pass by __syncthreads
            }
        }
    }
    for (int i = tid; i < 2048; i += 1024) hist[i] = 0u;
    __syncthreads();

    int npos = s_np + s_dn;
    int k = 3 * npos; if (k > P - 1) k = P - 1;
    if (tid == 0) {
        g_npos[b] = npos;
        g_fl[b] = s_dl;
        g_fc[b] = s_dc;
        s_krem = k;
    }
    __syncthreads();

    float acc = 0.0f;
    int c1 = 0, c2 = 0, c3 = 0;

    if (k > 0) {
        const uint4* v4 = reinterpret_cast<const uint4*>(g_ce + (long)b * P);
        uint4* sd4 = reinterpret_cast<uint4*>(sd);
        int P4 = P >> 2;

        // ---- pass A (vectorized): load uint4 + round-1 histogram ----
        for (int i = tid; i < P4; i += 1024) {
            uint4 u = v4[i];
            sd4[i] = u;
            atomicAdd(&hist[u.x >> 21], 1u);
            atomicAdd(&hist[u.y >> 21], 1u);
            atomicAdd(&hist[u.z >> 21], 1u);
            atomicAdd(&hist[u.w >> 21], 1u);
        }
        __syncthreads();

        // ---- selection helper: parallel suffix scan + crossing find ----
        #define SELECT_BIN(NBINS)                                               \
        {                                                                       \
            for (int i = tid; i < (NBINS); i += 1024) {                         \
                unsigned val = hist[i];                                         \
                _Pragma("unroll")                                               \
                for (int off = 1; off < 32; off <<= 1) {                        \
                    unsigned t2 = __shfl_down_sync(0xffffffffu, val, off);      \
                    if (lane + off < 32) val += t2;                             \
                }                                                               \
                sfx[i] = val;                                                   \
                if (lane == 0) csum[i >> 5] = val;                              \
            }                                                                   \
            __syncthreads();                                                    \
            int nch = (NBINS) >> 5;                                             \
            if (tid < nch) {                                                    \
                unsigned add = 0;                                               \
                for (int j = tid + 1; j < nch; j++) add += csum[j];             \
                cadd[tid] = add;                                                \
            }                                                                   \
            __syncthreads();                                                    \
            for (int i = tid; i < (NBINS); i += 1024) sfx[i] += cadd[i >> 5];   \
            __syncthreads();                                                    \
            int krem = s_krem;                                                  \
            for (int i = tid; i < (NBINS); i += 1024) {                         \
                unsigned s  = sfx[i];                                           \
                unsigned sn = (i + 1 < (NBINS)) ? sfx[i + 1] : 0u;              \
                if ((int)s >= krem && (int)sn < krem) {                         \
                    s_chosen = i; s_above = sn;                                 \
                }                                                               \
            }                                                                   \
            __syncthreads();                                                    \
            if (tid == 0) s_krem -= (int)s_above;                               \
        }

        SELECT_BIN(2048);
        c1 = s_chosen;
        for (int i = tid; i < 2048; i += 1024) hist[i] = 0u;
        __syncthreads();

        // ---- pass B (vectorized): bins>c1 → acc; ==c1 → compact + hist2 ----
        for (int i = tid; i < P4; i += 1024) {
            uint4 u = sd4[i];
            #pragma unroll
            for (int e = 0; e < 4; e++) {
                unsigned ue = (e == 0) ? u.x : (e == 1) ? u.y : (e == 2) ? u.z : u.w;
                int bin = (int)(ue >> 21);
                if (bin > c1) acc += __uint_as_float(ue);
                else if (bin == c1) {
                    unsigned pos = atomicAdd(&s_cnt1, 1u);
                    if (pos < BUF1) buf1[pos] = ue;
                    atomicAdd(&hist[(ue >> 10) & 0x7FFu], 1u);
                }
            }
        }
        __syncthreads();

        SELECT_BIN(2048);
        c2 = s_chosen;
        unsigned S1 = s_cnt1;
        if (tid < 1024) hist[tid] = 0u;
        __syncthreads();

        // ---- pass C: among survivors, bins2>c2 → acc, ==c2 → compact ----
        if (S1 <= BUF1) {
            for (unsigned i = tid; i < S1; i += 1024) {
                unsigned u = buf1[i];
                int bin2 = (int)((u >> 10) & 0x7FFu);
                if (bin2 > c2) acc += __uint_as_float(u);
                else if (bin2 == c2) {
                    unsigned pos = atomicAdd(&s_cnt2, 1u);
                    if (pos < BUF2) buf2[pos] = u;
                    atomicAdd(&hist[u & 0x3FFu], 1u);
                }
            }
        } else {
            for (int i = tid; i < P; i += 1024) {
                unsigned u = sd[i];
                if ((int)(u >> 21) != c1) continue;
                int bin2 = (int)((u >> 10) & 0x7FFu);
                if (bin2 > c2) acc += __uint_as_float(u);
                else if (bin2 == c2) {
                    unsigned pos = atomicAdd(&s_cnt2, 1u);
                    if (pos < BUF2) buf2[pos] = u;
                    atomicAdd(&hist[u & 0x3FFu], 1u);
                }
            }
        }
        __syncthreads();

        SELECT_BIN(1024);
        c3 = s_chosen;
        unsigned S2 = s_cnt2;
        __syncthreads();

        // ---- pass D: final strictly-greater among exact-tie bin ----
        if (S2 <= BUF2) {
            for (unsigned i = tid; i < S2; i += 1024) {
                unsigned u = buf2[i];
                if ((int)(u & 0x3FFu) > c3) acc += __uint_as_float(u);
            }
        } else {
            for (int i = tid; i < P; i += 1024) {
                unsigned u = sd[i];
                if ((int)(u >> 21) == c1 && (int)((u >> 10) & 0x7FFu) == c2 &&
                    (int)(u & 0x3FFu) > c3)
                    acc += __uint_as_float(u);
            }
        }

        // block reduce acc
        #pragma unroll
        for (int off = 16; off; off >>= 1)
            acc += __shfl_xor_sync(0xffffffffu, acc, off);
        if (lane == 0) fred[wrp] = acc;
        __syncthreads();
        if (tid == 0) {
            float tot = 0.f;
            #pragma unroll
            for (int w = 0; w < 32; w++) tot += fred[w];
            unsigned tbits = ((unsigned)c1 << 21) | ((unsigned)c2 << 10) | (unsigned)c3;
            g_cneg[b] = tot + (float)s_krem * __uint_as_float(tbits);
        }
    } else {
        if (tid == 0) g_cneg[b] = 0.0f;
    }

    // ---------------- last-block final reduction ----------------
    if (tid == 0) {
        __threadfence();
        unsigned old = atomicAdd(&g_done, 1u);
        s_last = (old == (unsigned)(B - 1));
    }
    __syncthreads();
    if (!s_last) return;
    __threadfence();

    double a = 0.0, cc = 0.0;
    int n = 0;
    int tot = B * nb;
    for (int i = tid; i < tot; i += 1024) { a += (double)g_pl[i]; cc += (double)g_pc[i]; }
    for (int i = tid; i < B; i += 1024) {
        a  += (double)g_fl[i];
        cc += (double)g_fc[i] + (double)g_cneg[i];
        n  += g_npos[i];
    }
    #pragma unroll
    for (int off = 16; off; off >>= 1) {
        a  += __shfl_xor_sync(0xffffffffu, a, off);
        cc += __shfl_xor_sync(0xffffffffu, cc, off);
        n  += __shfl_xor_sync(0xffffffffu, n, off);
    }
    if (lane == 0) { dredA[wrp] = a; dredC[wrp] = cc; ired[wrp] = n; }
    __syncthreads();
    if (tid == 0) {
        double ta = 0.0, tc = 0.0; int tn = 0;
        #pragma unroll
        for (int w = 0; w < 32; w++) { ta += dredA[w]; tc += dredC[w]; tn += ired[w]; }
        double N = (double)tn;
        if (N < 1.0) N = 1.0;
        out[0] = (float)(ta / N);
        out[1] = (float)(tc / N);
        g_done = 0u;                    // reset for next graph replay
    }
}

extern "C" void kernel_launch(void* const* d_in, const int* in_sizes, int n_in,
                              void* d_out, int out_size) {
    const float* loc     = (const float*)d_in[0];
    const float* conf    = (const float*)d_in[1];
    const float* priors  = (const float*)d_in[2];
    const float* targets = (const float*)d_in[3];
    float* out = (float*)d_out;

    int P = in_sizes[2] / 4;
    int B = in_sizes[0] / (P * 4);
    int O = in_sizes[3] / (B * 5);
    int nb = (P + 255) / 256;

    static int smem_set = 0;
    if (!smem_set) {
        cudaFuncSetAttribute(k_topk, cudaFuncAttributeMaxDynamicSharedMemorySize,
                             DSMEM_WORDS * 4);
        smem_set = 1;
    }

    dim3 grid(nb, B);
    k_main<<<grid, 256>>>(loc, conf, priors, targets, P, O);
    k_topk<<<B, 1024, (P + BUF1 + BUF2 + 2048 + 2048) * 4>>>(
        loc, conf, priors, targets, out, P, O, nb, B);
}

// round 8
// speedup vs baseline: 1.6616x; 1.3162x over previous
#include <cuda_runtime.h>

#define OVERLAP_T 0.5f
#define VAR0 0.1f
#define VAR1 0.2f

#define BMAX 64
#define PMAX 32768
#define OMAX 64
#define NBLK (PMAX/256)
#define BUF1 8192
#define BUF2 1024
// dynamic smem layout (uints): sd[PMAX] | buf1[BUF1] | buf2[BUF2] | hist[2048] | sfx[2048]
#define DSMEM_WORDS (PMAX + BUF1 + BUF2 + 2048 + 2048)

// Scratch (static device arrays; zero-initialized at load; each run leaves
// g_key/g_done zeroed again so graph replays see clean state)
__device__ float               g_ce[BMAX * PMAX];
__device__ unsigned long long  g_key[BMAX * OMAX];
__device__ int                 g_npos[BMAX];
__device__ float               g_pl[BMAX * NBLK];
__device__ float               g_pc[BMAX * NBLK];
__device__ int                 g_pn[BMAX * NBLK];
__device__ float               g_fl[BMAX];
__device__ float               g_fc[BMAX];
__device__ float               g_cneg[BMAX];
__device__ unsigned            g_done;

__device__ __forceinline__ float iou_one(float4 t, float ta,
                                         float px0, float py0, float px1, float py1,
                                         float pa) {
    float lx = fmaxf(t.x, px0), ly = fmaxf(t.y, py0);
    float rx = fminf(t.z, px1), ry = fminf(t.w, py1);
    float w = fmaxf(rx - lx, 0.0f), h = fmaxf(ry - ly, 0.0f);
    float inter = w * h;
    float den = ta + pa - inter;
    return __fdividef(inter, den);
}

__device__ __forceinline__ float sl1_of(float4 l, float4 pr, float4 t) {
    float gcx = ((t.x + t.z) * 0.5f - pr.x) / (VAR0 * pr.z);
    float gcy = ((t.y + t.w) * 0.5f - pr.y) / (VAR0 * pr.w);
    float gw  = __logf((t.z - t.x) / pr.z) * (1.0f / VAR1);
    float gh  = __logf((t.w - t.y) / pr.w) * (1.0f / VAR1);
    float d0 = l.x - gcx, d1 = l.y - gcy, d2 = l.z - gw, d3 = l.w - gh;
    float a0 = fabsf(d0), a1 = fabsf(d1), a2 = fabsf(d2), a3 = fabsf(d3);
    float s0 = (a0 < 1.0f) ? 0.5f * d0 * d0 : a0 - 0.5f;
    float s1 = (a1 < 1.0f) ? 0.5f * d1 * d1 : a1 - 0.5f;
    float s2 = (a2 < 1.0f) ? 0.5f * d2 * d2 : a2 - 0.5f;
    float s3 = (a3 < 1.0f) ? 0.5f * d3 * d3 : a3 - 0.5f;
    return (s0 + s1) + (s2 + s3);
}

__device__ __forceinline__ float lse2(float2 c) {
    float mx = fmaxf(c.x, c.y);
    float mn = fminf(c.x, c.y);
    return mx + __logf(1.0f + __expf(mn - mx));
}

// ---------------------------------------------------------------------------
// Fused match + loss. Per-truth warp argmax via REDUX.SYNC.MAX.U32; per-warp
// results go to private smem slots (no atomics in the loop); block epilogue
// folds 8 warp slots per truth and does one global atomicMax each.
// ---------------------------------------------------------------------------
__global__ __launch_bounds__(256)
void k_main(const float* __restrict__ loc,
            const float* __restrict__ conf,
            const float* __restrict__ priors,
            const float* __restrict__ targets,
            int P, int O) {
    int b    = blockIdx.y;
    int tid  = threadIdx.x;
    int lane = tid & 31;
    int wrp  = tid >> 5;
    int p    = blockIdx.x * blockDim.x + tid;

    __shared__ float4 tb[OMAX];
    __shared__ float  ta_s[OMAX];
    __shared__ unsigned long long wkey[8 * OMAX];   // [warp][o]

    if (tid < O) {
        const float* t = targets + ((long)b * O + tid) * 5;
        float4 v = make_float4(t[0], t[1], t[2], t[3]);
        tb[tid]   = v;
        ta_s[tid] = (v.z - v.x) * (v.w - v.y);
    }
    __syncthreads();

    float4 pr = reinterpret_cast<const float4*>(priors)[p];
    float px0 = pr.x - pr.z * 0.5f;
    float py0 = pr.y - pr.w * 0.5f;
    float px1 = pr.x + pr.z * 0.5f;
    float py1 = pr.y + pr.w * 0.5f;
    float pa  = (px1 - px0) * (py1 - py0);

    float best = -1.0f;
    int   besto = 0;
    int   pbase = blockIdx.x * blockDim.x + wrp * 32;

    #pragma unroll 4
    for (int o = 0; o < O; o++) {
        float iou = iou_one(tb[o], ta_s[o], px0, py0, px1, py1, pa);
        if (iou > best) { best = iou; besto = o; }

        // warp max + first-occurrence argmax (IoU >= 0 → u32 order == float order)
        unsigned ib = __float_as_uint(iou);
        unsigned m  = __reduce_max_sync(0xffffffffu, ib);
        unsigned win = __ballot_sync(0xffffffffu, ib == m);
        if (lane == 0) {
            int src = __ffs(win) - 1;
            wkey[wrp * OMAX + o] =
                ((unsigned long long)m << 32) |
                (unsigned int)(~(unsigned int)(pbase + src));
        }
    }

    long ip = (long)b * P + p;
    int ct = (best >= OVERLAP_T) ? 1 : 0;

    float2 c = reinterpret_cast<const float2*>(conf)[ip];
    float lse = lse2(c);

    float ll = 0.0f, cp = 0.0f, ce_neg;
    int np = 0;
    if (ct) {
        np = 1;
        cp = lse - c.y;
        ce_neg = 0.0f;
        float4 l = reinterpret_cast<const float4*>(loc)[ip];
        ll = sl1_of(l, pr, tb[besto]);
    } else {
        ce_neg = lse - c.x;
    }
    g_ce[ip] = ce_neg;

    #pragma unroll
    for (int off = 16; off; off >>= 1) {
        ll += __shfl_xor_sync(0xffffffffu, ll, off);
        cp += __shfl_xor_sync(0xffffffffu, cp, off);
        np += __shfl_xor_sync(0xffffffffu, np, off);
    }
    __shared__ float wl[8], wc[8];
    __shared__ int   wn[8];
    if (lane == 0) { wl[wrp] = ll; wc[wrp] = cp; wn[wrp] = np; }
    __syncthreads();
    if (tid == 0) {
        float a = 0.f, cc = 0.f; int nn = 0;
        #pragma unroll
        for (int w = 0; w < 8; w++) { a += wl[w]; cc += wc[w]; nn += wn[w]; }
        int bi = b * gridDim.x + blockIdx.x;
        g_pl[bi] = a; g_pc[bi] = cc; g_pn[bi] = nn;
    }
    if (tid < O) {
        unsigned long long bk = wkey[tid];
        #pragma unroll
        for (int w = 1; w < 8; w++) {
            unsigned long long k2 = wkey[w * OMAX + tid];
            if (k2 > bk) bk = k2;
        }
        atomicMax(&g_key[b * OMAX + tid], bk);
    }
}

// ---------------------------------------------------------------------------
// Fused fixup + radix-select top-k + (last block) final reduction.
// Passes A/B vectorized (uint4); plain per-element smem atomics.
// ---------------------------------------------------------------------------
__global__ __launch_bounds__(1024)
void k_topk(const float* __restrict__ loc,
            const float* __restrict__ conf,
            const float* __restrict__ priors,
            const float* __restrict__ targets,
            float* __restrict__ out,
            int P, int O, int nb, int B) {
    extern __shared__ unsigned dyn[];
    unsigned* sd   = dyn;                 // P staged values
    unsigned* buf1 = dyn + P;             // BUF1
    unsigned* buf2 = buf1 + BUF1;         // BUF2
    unsigned* hist = buf2 + BUF2;         // 2048
    unsigned* sfx  = hist + 2048;         // 2048

    __shared__ unsigned csum[64], cadd[64];
    __shared__ int      ps[OMAX];
    __shared__ float    fred[32];
    __shared__ int      ired[32];
    __shared__ double   dredA[32], dredC[32];
    __shared__ float    s_dl, s_dc;
    __shared__ int      s_dn, s_np, s_krem, s_chosen, s_last;
    __shared__ unsigned s_above, s_cnt1, s_cnt2;

    int b    = blockIdx.x;
    int tid  = threadIdx.x;
    int lane = tid & 31;
    int wrp  = tid >> 5;

    // ---------------- fixup prologue ----------------
    if (tid == 0) { s_dl = 0.f; s_dc = 0.f; s_dn = 0; s_cnt1 = 0u; s_cnt2 = 0u; }
    int np = 0;
    for (int j = tid; j < nb; j += 1024) np += g_pn[b * nb + j];
    #pragma unroll
    for (int off = 16; off; off >>= 1) np += __shfl_xor_sync(0xffffffffu, np, off);
    if (lane == 0) ired[wrp] = np;
    if (tid < O) {
        ps[tid] = (int)(~(unsigned int)(g_key[b * OMAX + tid] & 0xffffffffull));
        g_key[b * OMAX + tid] = 0ull;   // reset for next graph replay
    }
    __syncthreads();
    if (tid == 0) {
        int acc0 = 0;
        #pragma unroll
        for (int w = 0; w < 32; w++) acc0 += ired[w];
        s_np = acc0;
    }

    if (tid < O) {
        int p = ps[tid];
        bool dup = false;
        for (int o2 = tid + 1; o2 < O; o2++) if (ps[o2] == p) dup = true;
        if (!dup) {
            float4 pr = reinterpret_cast<const float4*>(priors)[p];
            float px0 = pr.x - pr.z * 0.5f;
            float py0 = pr.y - pr.w * 0.5f;
            float px1 = pr.x + pr.z * 0.5f;
            float py1 = pr.y + pr.w * 0.5f;
            float pa  = (px1 - px0) * (py1 - py0);

            float best = -1.0f; int bo = 0;
            for (int oo = 0; oo < O; oo++) {
                const float* tt = targets + ((long)b * O + oo) * 5;
                float4 t = make_float4(tt[0], tt[1], tt[2], tt[3]);
                float ta = (t.z - t.x) * (t.w - t.y);
                float iou = iou_one(t, ta, px0, py0, px1, py1, pa);
                if (iou > best) { best = iou; bo = oo; }
            }
            int ct = (best >= OVERLAP_T) ? 1 : 0;

            long ip = (long)b * P + p;
            float4 l = reinterpret_cast<const float4*>(loc)[ip];
            const float* tf = targets + ((long)b * O + tid) * 5;
            float4 tnew = make_float4(tf[0], tf[1], tf[2], tf[3]);
            float sl_new = sl1_of(l, pr, tnew);

            if (ct) {
                const float* to = targets + ((long)b * O + bo) * 5;
                float4 told = make_float4(to[0], to[1], to[2], to[3]);
                atomicAdd(&s_dl, sl_new - sl1_of(l, pr, told));
            } else {
                float2 c = reinterpret_cast<const float2*>(conf)[ip];
                float lse = lse2(c);
                atomicAdd(&s_dl, sl_new);
                atomicAdd(&s_dc, lse - c.y);
                atomicAdd(&s_dn, 1);
                g_ce[ip] = 0.0f;   // ordered before the load pass by __syncthreads
            }
        }
    }
    for (int i = tid; i < 2048; i += 1024) hist[i] = 0u;
    __syncthreads();

    int npos = s_np + s_dn;
    int k = 3 * npos; if (k > P - 1) k = P - 1;
    if (tid == 0) {
        g_npos[b] = npos;
        g_fl[b] = s_dl;
        g_fc[b] = s_dc;
        s_krem = k;
    }
    __syncthreads();

    float acc = 0.0f;
    int c1 = 0, c2 = 0, c3 = 0;

    if (k > 0) {
        const uint4* v4 = reinterpret_cast<const uint4*>(g_ce + (long)b * P);
        uint4* sd4 = reinterpret_cast<uint4*>(sd);
        int P4 = P >> 2;

        // ---- pass A (vectorized): load uint4 + round-1 histogram ----
        for (int i = tid; i < P4; i += 1024) {
            uint4 u = v4[i];
            sd4[i] = u;
            atomicAdd(&hist[u.x >> 21], 1u);
            atomicAdd(&hist[u.y >> 21], 1u);
            atomicAdd(&hist[u.z >> 21], 1u);
            atomicAdd(&hist[u.w >> 21], 1u);
        }
        __syncthreads();

        // ---- selection helper: parallel suffix scan + crossing find ----
        #define SELECT_BIN(NBINS)                                               \
        {                                                                       \
            for (int i = tid; i < (NBINS); i += 1024) {                         \
                unsigned val = hist[i];                                         \
                _Pragma("unroll")                                               \
                for (int off = 1; off < 32; off <<= 1) {                        \
                    unsigned t2 = __shfl_down_sync(0xffffffffu, val, off);      \
                    if (lane + off < 32) val += t2;                             \
                }                                                               \
                sfx[i] = val;                                                   \
                if (lane == 0) csum[i >> 5] = val;                              \
            }                                                                   \
            __syncthreads();                                                    \
            int nch = (NBINS) >> 5;                                             \
            if (tid < nch) {                                                    \
                unsigned add = 0;                                               \
                for (int j = tid + 1; j < nch; j++) add += csum[j];             \
                cadd[tid] = add;                                                \
            }                                                                   \
            __syncthreads();                                                    \
            for (int i = tid; i < (NBINS); i += 1024) sfx[i] += cadd[i >> 5];   \
            __syncthreads();                                                    \
            int krem = s_krem;                                                  \
            for (int i = tid; i < (NBINS); i += 1024) {                         \
                unsigned s  = sfx[i];                                           \
                unsigned sn = (i + 1 < (NBINS)) ? sfx[i + 1] : 0u;              \
                if ((int)s >= krem && (int)sn < krem) {                         \
                    s_chosen = i; s_above = sn;                                 \
                }                                                               \
            }                                                                   \
            __syncthreads();                                                    \
            if (tid == 0) s_krem -= (int)s_above;                               \
        }

        SELECT_BIN(2048);
        c1 = s_chosen;
        for (int i = tid; i < 2048; i += 1024) hist[i] = 0u;
        __syncthreads();

        // ---- pass B (vectorized): bins>c1 → acc; ==c1 → compact + hist2 ----
        for (int i = tid; i < P4; i += 1024) {
            uint4 u = sd4[i];
            #pragma unroll
            for (int e = 0; e < 4; e++) {
                unsigned ue = (e == 0) ? u.x : (e == 1) ? u.y : (e == 2) ? u.z : u.w;
                int bin = (int)(ue >> 21);
                if (bin > c1) acc += __uint_as_float(ue);
                else if (bin == c1) {
                    unsigned pos = atomicAdd(&s_cnt1, 1u);
                    if (pos < BUF1) buf1[pos] = ue;
                    atomicAdd(&hist[(ue >> 10) & 0x7FFu], 1u);
                }
            }
        }
        __syncthreads();

        SELECT_BIN(2048);
        c2 = s_chosen;
        unsigned S1 = s_cnt1;
        if (tid < 1024) hist[tid] = 0u;
        __syncthreads();

        // ---- pass C: among survivors, bins2>c2 → acc, ==c2 → compact ----
        if (S1 <= BUF1) {
            for (unsigned i = tid; i < S1; i += 1024) {
                unsigned u = buf1[i];
                int bin2 = (int)((u >> 10) & 0x7FFu);
                if (bin2 > c2) acc += __uint_as_float(u);
                else if (bin2 == c2) {
                    unsigned pos = atomicAdd(&s_cnt2, 1u);
                    if (pos < BUF2) buf2[pos] = u;
                    atomicAdd(&hist[u & 0x3FFu], 1u);
                }
            }
        } else {
            for (int i = tid; i < P; i += 1024) {
                unsigned u = sd[i];
                if ((int)(u >> 21) != c1) continue;
                int bin2 = (int)((u >> 10) & 0x7FFu);
                if (bin2 > c2) acc += __uint_as_float(u);
                else if (bin2 == c2) {
                    unsigned pos = atomicAdd(&s_cnt2, 1u);
                    if (pos < BUF2) buf2[pos] = u;
                    atomicAdd(&hist[u & 0x3FFu], 1u);
                }
            }
        }
        __syncthreads();

        SELECT_BIN(1024);
        c3 = s_chosen;
        unsigned S2 = s_cnt2;
        __syncthreads();

        // ---- pass D: final strictly-greater among exact-tie bin ----
        if (S2 <= BUF2) {
            for (unsigned i = tid; i < S2; i += 1024) {
                unsigned u = buf2[i];
                if ((int)(u & 0x3FFu) > c3) acc += __uint_as_float(u);
            }
        } else {
            for (int i = tid; i < P; i += 1024) {
                unsigned u = sd[i];
                if ((int)(u >> 21) == c1 && (int)((u >> 10) & 0x7FFu) == c2 &&
                    (int)(u & 0x3FFu) > c3)
                    acc += __uint_as_float(u);
            }
        }

        // block reduce acc
        #pragma unroll
        for (int off = 16; off; off >>= 1)
            acc += __shfl_xor_sync(0xffffffffu, acc, off);
        if (lane == 0) fred[wrp] = acc;
        __syncthreads();
        if (tid == 0) {
            float tot = 0.f;
            #pragma unroll
            for (int w = 0; w < 32; w++) tot += fred[w];
            unsigned tbits = ((unsigned)c1 << 21) | ((unsigned)c2 << 10) | (unsigned)c3;
            g_cneg[b] = tot + (float)s_krem * __uint_as_float(tbits);
        }
    } else {
        if (tid == 0) g_cneg[b] = 0.0f;
    }

    // ---------------- last-block final reduction ----------------
    if (tid == 0) {
        __threadfence();
        unsigned old = atomicAdd(&g_done, 1u);
        s_last = (old == (unsigned)(B - 1));
    }
    __syncthreads();
    if (!s_last) return;
    __threadfence();

    double a = 0.0, cc = 0.0;
    int n = 0;
    int tot = B * nb;
    for (int i = tid; i < tot; i += 1024) { a += (double)g_pl[i]; cc += (double)g_pc[i]; }
    for (int i = tid; i < B; i += 1024) {
        a  += (double)g_fl[i];
        cc += (double)g_fc[i] + (double)g_cneg[i];
        n  += g_npos[i];
    }
    #pragma unroll
    for (int off = 16; off; off >>= 1) {
        a  += __shfl_xor_sync(0xffffffffu, a, off);
        cc += __shfl_xor_sync(0xffffffffu, cc, off);
        n  += __shfl_xor_sync(0xffffffffu, n, off);
    }
    if (lane == 0) { dredA[wrp] = a; dredC[wrp] = cc; ired[wrp] = n; }
    __syncthreads();
    if (tid == 0) {
        double ta = 0.0, tc = 0.0; int tn = 0;
        #pragma unroll
        for (int w = 0; w < 32; w++) { ta += dredA[w]; tc += dredC[w]; tn += ired[w]; }
        double N = (double)tn;
        if (N < 1.0) N = 1.0;
        out[0] = (float)(ta / N);
        out[1] = (float)(tc / N);
        g_done = 0u;                    // reset for next graph replay
    }
}

extern "C" void kernel_launch(void* const* d_in, const int* in_sizes, int n_in,
                              void* d_out, int out_size) {
    const float* loc     = (const float*)d_in[0];
    const float* conf    = (const float*)d_in[1];
    const float* priors  = (const float*)d_in[2];
    const float* targets = (const float*)d_in[3];
    float* out = (float*)d_out;

    int P = in_sizes[2] / 4;
    int B = in_sizes[0] / (P * 4);
    int O = in_sizes[3] / (B * 5);
    int nb = (P + 255) / 256;

    static int smem_set = 0;
    if (!smem_set) {
        cudaFuncSetAttribute(k_topk, cudaFuncAttributeMaxDynamicSharedMemorySize,
                             DSMEM_WORDS * 4);
        smem_set = 1;
    }

    dim3 grid(nb, B);
    k_main<<<grid, 256>>>(loc, conf, priors, targets, P, O);
    k_topk<<<B, 1024, (P + BUF1 + BUF2 + 2048 + 2048) * 4>>>(
        loc, conf, priors, targets, out, P, O, nb, B);
}